// round 9
// baseline (speedup 1.0000x reference)
#include <cuda_runtime.h>
#include <cuda_bf16.h>
#include <math.h>

// ---------------------------------------------------------------------------
// InstantNGP hash-grid embedding, 16 levels, F=2, T=2^19, 1M points.
//
// R9 = R6 (325.7us: full unroll, register accumulators r[16], per-level
// barrier, float4 pair-loads + predicated odd float2 loads) + ONE change:
// end-of-kernel smem-staged COALESCED stores.
//
// R6's tail wrote each thread's own 128B output line directly (8x STG.128,
// 32 wavefronts each = 256 store wavefronts/warp, ~7% of all L1 work; L1 is
// the binding pipe at 91.3%). Now: after the (unchanged) level loop, spill
// r[16] to smem rows of stride 33 (scalar STS, conflict-free), then a
// block-strided copy-out does conflict-free LDS + fully coalesced STG.32
// (~96 wavefront-cycles/warp). The level loop itself is untouched — the
// R4/R5 regression came from IN-LOOP staging letting ptxas drop r[] and
// collapse gather MLP (regs 73 -> 40); end staging keeps regs/schedule.
// ---------------------------------------------------------------------------

#define NLVL 16
#define LOG2_T 19
#define TABLE_SIZE (1u << LOG2_T)
#define HMASK (TABLE_SIZE - 1u)
#define BSZ 1048576
#define PRIME1 2654435761u
#define PRIME2 805459861u
#define TPB 256
#define SROW 33   // odd stride => bank (tid + c) & 31, conflict-free both phases

struct LevelParams {
    float invgs;   // 1 / grid_size (host-computed via double)
    float resm1;   // (float)(res - 1)
};
struct AllParams {
    LevelParams lp[NLVL];
};

__global__ __launch_bounds__(TPB)
void hash_embed_kernel(const float* __restrict__ x,
                       const float* __restrict__ emb,
                       float* __restrict__ out,
                       AllParams P)
{
    __shared__ float s[TPB * SROW];

    const int tid = threadIdx.x;
    const int p = blockIdx.x * TPB + tid;   // BSZ % TPB == 0

    const float x0 = x[p * 3 + 0];
    const float x1 = x[p * 3 + 1];
    const float x2 = x[p * 3 + 2];

    float2 r[NLVL];

#pragma unroll
    for (int l = 0; l < NLVL; ++l) {
        const float invgs = P.lp[l].invgs;
        const float rm1   = P.lp[l].resm1;

        const float rel0 = (x0 + 1.0f) * invgs;
        const float rel1 = (x1 + 1.0f) * invgs;
        const float rel2 = (x2 + 1.0f) * invgs;

        const float f0 = fminf(fmaxf(floorf(rel0), 0.0f), rm1);
        const float f1 = fminf(fmaxf(floorf(rel1), 0.0f), rm1);
        const float f2 = fminf(fmaxf(floorf(rel2), 0.0f), rm1);

        const float w0 = rel0 - f0;
        const float w1 = rel1 - f1;
        const float w2 = rel2 - f2;

        const unsigned u0 = (unsigned)f0;
        const unsigned u1 = (unsigned)f1;
        const unsigned u2 = (unsigned)f2;

        const bool odd0 = (u0 & 1u) != 0u;

        const unsigned a1 = u0 + 1u;
        const unsigned b0 = u1 * PRIME1;
        const unsigned b1 = b0 + PRIME1;
        const unsigned c0 = u2 * PRIME2;
        const unsigned c1 = c0 + PRIME2;

        const float2* __restrict__ tab =
            (const float2*)emb + (size_t)l * TABLE_SIZE;
        const float4* __restrict__ tab4 = (const float4*)tab;

        // x-corner-0 hash per (y,z) combo; for even u0 the aligned pair
        // {h, h^1} holds BOTH x-corners.
        const unsigned h00 = (u0 ^ b0 ^ c0) & HMASK;
        const unsigned h10 = (u0 ^ b1 ^ c0) & HMASK;
        const unsigned h01 = (u0 ^ b0 ^ c1) & HMASK;
        const unsigned h11 = (u0 ^ b1 ^ c1) & HMASK;

        // 4 unconditional float4 pair-loads — independent, one round
        const float4 q00 = __ldg(&tab4[h00 >> 1]);
        const float4 q10 = __ldg(&tab4[h10 >> 1]);
        const float4 q01 = __ldg(&tab4[h01 >> 1]);
        const float4 q11 = __ldg(&tab4[h11 >> 1]);

        // 4 predicated float2 loads for odd u0 — same latency round
        float2 e00, e10, e01, e11;
        if (odd0) {
            e00 = __ldg(&tab[(a1 ^ b0 ^ c0) & HMASK]);
            e10 = __ldg(&tab[(a1 ^ b1 ^ c0) & HMASK]);
            e01 = __ldg(&tab[(a1 ^ b0 ^ c1) & HMASK]);
            e11 = __ldg(&tab[(a1 ^ b1 ^ c1) & HMASK]);
        } else {
            e00 = e10 = e01 = e11 = make_float2(0.0f, 0.0f);
        }

        const bool o00 = (h00 & 1u) != 0u;
        const bool o10 = (h10 & 1u) != 0u;
        const bool o01 = (h01 & 1u) != 0u;
        const bool o11 = (h11 & 1u) != 0u;

        const float2 vA00 = o00 ? make_float2(q00.z, q00.w) : make_float2(q00.x, q00.y);
        const float2 vA10 = o10 ? make_float2(q10.z, q10.w) : make_float2(q10.x, q10.y);
        const float2 vA01 = o01 ? make_float2(q01.z, q01.w) : make_float2(q01.x, q01.y);
        const float2 vA11 = o11 ? make_float2(q11.z, q11.w) : make_float2(q11.x, q11.y);

        const float2 vB00 = odd0 ? e00 : (o00 ? make_float2(q00.x, q00.y) : make_float2(q00.z, q00.w));
        const float2 vB10 = odd0 ? e10 : (o10 ? make_float2(q10.x, q10.y) : make_float2(q10.z, q10.w));
        const float2 vB01 = odd0 ? e01 : (o01 ? make_float2(q01.x, q01.y) : make_float2(q01.z, q01.w));
        const float2 vB11 = odd0 ? e11 : (o11 ? make_float2(q11.x, q11.y) : make_float2(q11.z, q11.w));

        const float m0 = 1.0f - w0;
        const float m1 = 1.0f - w1;
        const float m2 = 1.0f - w2;

        const float p00 = m1 * m2;
        const float p10 = w1 * m2;
        const float p01 = m1 * w2;
        const float p11 = w1 * w2;

        const float cx00x = fmaf(w0, vB00.x, m0 * vA00.x);
        const float cx00y = fmaf(w0, vB00.y, m0 * vA00.y);
        const float cx10x = fmaf(w0, vB10.x, m0 * vA10.x);
        const float cx10y = fmaf(w0, vB10.y, m0 * vA10.y);
        const float cx01x = fmaf(w0, vB01.x, m0 * vA01.x);
        const float cx01y = fmaf(w0, vB01.y, m0 * vA01.y);
        const float cx11x = fmaf(w0, vB11.x, m0 * vA11.x);
        const float cx11y = fmaf(w0, vB11.y, m0 * vA11.y);

        float accx = p00 * cx00x;
        float accy = p00 * cx00y;
        accx = fmaf(p10, cx10x, accx);
        accy = fmaf(p10, cx10y, accy);
        accx = fmaf(p01, cx01x, accx);
        accy = fmaf(p01, cx01y, accy);
        accx = fmaf(p11, cx11x, accx);
        accy = fmaf(p11, cx11y, accy);

        r[l].x = accx;
        r[l].y = accy;

        // same per-level phase-locking as R6 (known-good)
        __syncthreads();
    }

    // ---- end-of-kernel store staging (the only change vs R6) ----
    // scalar STS, stride-33 rows: bank (tid + c) & 31 -> conflict-free
    {
        float* srow = &s[tid * SROW];
#pragma unroll
        for (int l = 0; l < NLVL; ++l) {
            srow[2 * l]     = r[l].x;
            srow[2 * l + 1] = r[l].y;
        }
    }
    __syncthreads();

    // copy-out: lane e reads element e of one point's row (banks
    // (row + e) & 31 distinct -> conflict-free LDS); warp's STG.32 covers
    // one contiguous 128B line -> 1 wavefront per iteration.
    const int base = blockIdx.x * (TPB * 32);
#pragma unroll
    for (int k = tid; k < TPB * 32; k += TPB) {
        out[base + k] = s[(k >> 5) * SROW + (k & 31)];
    }
}

extern "C" void kernel_launch(void* const* d_in, const int* in_sizes, int n_in,
                              void* d_out, int out_size)
{
    const float* x   = (const float*)d_in[0];   // (1048576, 3) f32
    const float* emb = (const float*)d_in[1];   // (16, 524288, 2) f32
    float* out = (float*)d_out;                 // (1048576, 32) f32

    // Recompute RESOLUTIONS with the reference's double-precision formula
    // (several floor() results sit exactly on integer boundaries).
    AllParams P;
    const double growth = exp((log(512.0) - log(16.0)) / 15.0);
    for (int i = 0; i < NLVL; ++i) {
        int res = (int)floor(16.0 * pow(growth, (double)i));
        float gsf = (float)(2.0 / (double)res);
        P.lp[i].invgs = (float)(1.0 / (double)gsf);
        P.lp[i].resm1 = (float)(res - 1);
    }

    dim3 grid(BSZ / TPB);
    dim3 block(TPB);
    hash_embed_kernel<<<grid, block>>>(x, emb, out, P);
}

// round 11
// speedup vs baseline: 1.1615x; 1.1615x over previous
#include <cuda_runtime.h>
#include <cuda_bf16.h>
#include <math.h>

// ---------------------------------------------------------------------------
// InstantNGP hash-grid embedding, 16 levels, F=2, T=2^19, 1M points.
//
// R10 = R6 compute kernel (325.7us config: full unroll, register accumulators,
// per-level barrier, float4 pair-loads + predicated odd float2 loads, direct
// STG.128 tail) fed by a SPATIAL COUNTING SORT so that warp lanes are
// spatially adjacent points:
//   L1 wavefront cost = distinct 128B lines per warp. Random lanes => 32
//   distinct lines per gather. Sorted into a 32^3 Morton grid (one warp ~ one
//   bin), levels with res<=32 collapse to ~2-4 lines/gather and mid levels
//   partially dedup => ~25% less total L1 work (L1 is the binding pipe, 90%).
// Pipeline (all graph-capturable, scratch = __device__ globals):
//   K1 zero 32768-bin histogram
//   K2 histogram of Morton(cell) keys (atomics spread over 32768 L2 addrs)
//   K3 single-block exclusive scan (32768 bins)
//   K4 atomic scatter -> g_perm (intra-bin order arbitrary; output per
//      ORIGINAL index, so results are order-independent/deterministic)
//   K5 main embedding kernel on permuted points
// ---------------------------------------------------------------------------

#define NLVL 16
#define LOG2_T 19
#define TABLE_SIZE (1u << LOG2_T)
#define HMASK (TABLE_SIZE - 1u)
#define BSZ 1048576
#define PRIME1 2654435761u
#define PRIME2 805459861u
#define TPB 256
#define GRID_BITS 5
#define GRID_RES 32               // 32^3 sort bins
#define NBINS (GRID_RES * GRID_RES * GRID_RES)

__device__ unsigned g_hist[NBINS];
__device__ unsigned g_perm[BSZ];

struct LevelParams {
    float invgs;   // 1 / grid_size (host-computed via double)
    float resm1;   // (float)(res - 1)
};
struct AllParams {
    LevelParams lp[NLVL];
};

// ---- Morton key helpers ----------------------------------------------------
__device__ __forceinline__ unsigned expand3(unsigned v) {
    // spread 10 (we use 5) low bits to every 3rd bit
    v &= 0x3FFu;
    v = (v | (v << 16)) & 0x030000FFu;
    v = (v | (v << 8))  & 0x0300F00Fu;
    v = (v | (v << 4))  & 0x030C30C3u;
    v = (v | (v << 2))  & 0x09249249u;
    return v;
}

__device__ __forceinline__ unsigned point_key(float x0, float x1, float x2) {
    unsigned c0 = (unsigned)fminf(fmaxf(floorf((x0 + 1.0f) * 16.0f), 0.0f), 31.0f);
    unsigned c1 = (unsigned)fminf(fmaxf(floorf((x1 + 1.0f) * 16.0f), 0.0f), 31.0f);
    unsigned c2 = (unsigned)fminf(fmaxf(floorf((x2 + 1.0f) * 16.0f), 0.0f), 31.0f);
    return expand3(c0) | (expand3(c1) << 1) | (expand3(c2) << 2);
}

// ---- K1: zero histogram ----------------------------------------------------
__global__ void zero_hist_kernel() {
    int i = blockIdx.x * blockDim.x + threadIdx.x;
    if (i < NBINS) g_hist[i] = 0u;
}

// ---- K2: histogram ---------------------------------------------------------
__global__ __launch_bounds__(TPB)
void hist_kernel(const float* __restrict__ x) {
    int i = blockIdx.x * TPB + threadIdx.x;
    const float x0 = x[i * 3 + 0];
    const float x1 = x[i * 3 + 1];
    const float x2 = x[i * 3 + 2];
    atomicAdd(&g_hist[point_key(x0, x1, x2)], 1u);
}

// ---- K3: single-block exclusive scan over NBINS ----------------------------
__global__ __launch_bounds__(1024)
void scan_kernel() {
    __shared__ unsigned sums[1024];
    const int t = threadIdx.x;
    const int base = t * (NBINS / 1024);          // 32 bins per thread

    unsigned local[NBINS / 1024];
    unsigned run = 0;
#pragma unroll
    for (int j = 0; j < NBINS / 1024; ++j) {
        local[j] = run;
        run += g_hist[base + j];
    }
    sums[t] = run;
    __syncthreads();

    // Hillis-Steele inclusive scan (read before write each step)
    for (int off = 1; off < 1024; off <<= 1) {
        unsigned v = (t >= off) ? sums[t - off] : 0u;
        __syncthreads();
        sums[t] += v;
        __syncthreads();
    }
    const unsigned prefix = sums[t] - run;        // exclusive prefix of this chunk

#pragma unroll
    for (int j = 0; j < NBINS / 1024; ++j)
        g_hist[base + j] = prefix + local[j];
}

// ---- K4: scatter (build permutation) ---------------------------------------
__global__ __launch_bounds__(TPB)
void scatter_kernel(const float* __restrict__ x) {
    int i = blockIdx.x * TPB + threadIdx.x;
    const float x0 = x[i * 3 + 0];
    const float x1 = x[i * 3 + 1];
    const float x2 = x[i * 3 + 2];
    unsigned slot = atomicAdd(&g_hist[point_key(x0, x1, x2)], 1u);
    g_perm[slot] = (unsigned)i;
}

// ---- K5: main embedding kernel (R6 body on permuted points) ----------------
__global__ __launch_bounds__(TPB)
void hash_embed_kernel(const float* __restrict__ x,
                       const float* __restrict__ emb,
                       float* __restrict__ out,
                       AllParams P)
{
    const int i = blockIdx.x * TPB + threadIdx.x;   // BSZ % TPB == 0
    const unsigned p = g_perm[i];

    const float x0 = __ldg(&x[p * 3 + 0]);
    const float x1 = __ldg(&x[p * 3 + 1]);
    const float x2 = __ldg(&x[p * 3 + 2]);

    float2 r[NLVL];

#pragma unroll
    for (int l = 0; l < NLVL; ++l) {
        const float invgs = P.lp[l].invgs;
        const float rm1   = P.lp[l].resm1;

        const float rel0 = (x0 + 1.0f) * invgs;
        const float rel1 = (x1 + 1.0f) * invgs;
        const float rel2 = (x2 + 1.0f) * invgs;

        const float f0 = fminf(fmaxf(floorf(rel0), 0.0f), rm1);
        const float f1 = fminf(fmaxf(floorf(rel1), 0.0f), rm1);
        const float f2 = fminf(fmaxf(floorf(rel2), 0.0f), rm1);

        const float w0 = rel0 - f0;
        const float w1 = rel1 - f1;
        const float w2 = rel2 - f2;

        const unsigned u0 = (unsigned)f0;
        const unsigned u1 = (unsigned)f1;
        const unsigned u2 = (unsigned)f2;

        const bool odd0 = (u0 & 1u) != 0u;

        const unsigned a1 = u0 + 1u;
        const unsigned b0 = u1 * PRIME1;
        const unsigned b1 = b0 + PRIME1;
        const unsigned c0 = u2 * PRIME2;
        const unsigned c1 = c0 + PRIME2;

        const float2* __restrict__ tab =
            (const float2*)emb + (size_t)l * TABLE_SIZE;
        const float4* __restrict__ tab4 = (const float4*)tab;

        // x-corner-0 hash per (y,z) combo; for even u0 the aligned pair
        // {h, h^1} holds BOTH x-corners.
        const unsigned h00 = (u0 ^ b0 ^ c0) & HMASK;
        const unsigned h10 = (u0 ^ b1 ^ c0) & HMASK;
        const unsigned h01 = (u0 ^ b0 ^ c1) & HMASK;
        const unsigned h11 = (u0 ^ b1 ^ c1) & HMASK;

        // 4 unconditional float4 pair-loads — independent, one round
        const float4 q00 = __ldg(&tab4[h00 >> 1]);
        const float4 q10 = __ldg(&tab4[h10 >> 1]);
        const float4 q01 = __ldg(&tab4[h01 >> 1]);
        const float4 q11 = __ldg(&tab4[h11 >> 1]);

        // 4 predicated float2 loads for odd u0 — same latency round
        float2 e00, e10, e01, e11;
        if (odd0) {
            e00 = __ldg(&tab[(a1 ^ b0 ^ c0) & HMASK]);
            e10 = __ldg(&tab[(a1 ^ b1 ^ c0) & HMASK]);
            e01 = __ldg(&tab[(a1 ^ b0 ^ c1) & HMASK]);
            e11 = __ldg(&tab[(a1 ^ b1 ^ c1) & HMASK]);
        } else {
            e00 = e10 = e01 = e11 = make_float2(0.0f, 0.0f);
        }

        const bool o00 = (h00 & 1u) != 0u;
        const bool o10 = (h10 & 1u) != 0u;
        const bool o01 = (h01 & 1u) != 0u;
        const bool o11 = (h11 & 1u) != 0u;

        const float2 vA00 = o00 ? make_float2(q00.z, q00.w) : make_float2(q00.x, q00.y);
        const float2 vA10 = o10 ? make_float2(q10.z, q10.w) : make_float2(q10.x, q10.y);
        const float2 vA01 = o01 ? make_float2(q01.z, q01.w) : make_float2(q01.x, q01.y);
        const float2 vA11 = o11 ? make_float2(q11.z, q11.w) : make_float2(q11.x, q11.y);

        const float2 vB00 = odd0 ? e00 : (o00 ? make_float2(q00.x, q00.y) : make_float2(q00.z, q00.w));
        const float2 vB10 = odd0 ? e10 : (o10 ? make_float2(q10.x, q10.y) : make_float2(q10.z, q10.w));
        const float2 vB01 = odd0 ? e01 : (o01 ? make_float2(q01.x, q01.y) : make_float2(q01.z, q01.w));
        const float2 vB11 = odd0 ? e11 : (o11 ? make_float2(q11.x, q11.y) : make_float2(q11.z, q11.w));

        const float m0 = 1.0f - w0;
        const float m1 = 1.0f - w1;
        const float m2 = 1.0f - w2;

        const float p00 = m1 * m2;
        const float p10 = w1 * m2;
        const float p01 = m1 * w2;
        const float p11 = w1 * w2;

        const float cx00x = fmaf(w0, vB00.x, m0 * vA00.x);
        const float cx00y = fmaf(w0, vB00.y, m0 * vA00.y);
        const float cx10x = fmaf(w0, vB10.x, m0 * vA10.x);
        const float cx10y = fmaf(w0, vB10.y, m0 * vA10.y);
        const float cx01x = fmaf(w0, vB01.x, m0 * vA01.x);
        const float cx01y = fmaf(w0, vB01.y, m0 * vA01.y);
        const float cx11x = fmaf(w0, vB11.x, m0 * vA11.x);
        const float cx11y = fmaf(w0, vB11.y, m0 * vA11.y);

        float accx = p00 * cx00x;
        float accy = p00 * cx00y;
        accx = fmaf(p10, cx10x, accx);
        accy = fmaf(p10, cx10y, accy);
        accx = fmaf(p01, cx01x, accx);
        accy = fmaf(p01, cx01y, accy);
        accx = fmaf(p11, cx11x, accx);
        accy = fmaf(p11, cx11y, accy);

        r[l].x = accx;
        r[l].y = accy;

        // per-level phase-locking (known-good; stronger now that warps are
        // spatially coherent)
        __syncthreads();
    }

    // direct per-thread output (R6 tail; R9 proved store staging is neutral,
    // and with a permuted p it couldn't coalesce anyway)
    float4* __restrict__ o = (float4*)(out + (size_t)p * 32);
#pragma unroll
    for (int k = 0; k < 8; ++k) {
        o[k] = make_float4(r[2 * k].x, r[2 * k].y,
                           r[2 * k + 1].x, r[2 * k + 1].y);
    }
}

extern "C" void kernel_launch(void* const* d_in, const int* in_sizes, int n_in,
                              void* d_out, int out_size)
{
    const float* x   = (const float*)d_in[0];   // (1048576, 3) f32
    const float* emb = (const float*)d_in[1];   // (16, 524288, 2) f32
    float* out = (float*)d_out;                 // (1048576, 32) f32

    // Recompute RESOLUTIONS with the reference's double-precision formula
    // (several floor() results sit exactly on integer boundaries).
    AllParams P;
    const double growth = exp((log(512.0) - log(16.0)) / 15.0);
    for (int i = 0; i < NLVL; ++i) {
        int res = (int)floor(16.0 * pow(growth, (double)i));
        float gsf = (float)(2.0 / (double)res);
        P.lp[i].invgs = (float)(1.0 / (double)gsf);
        P.lp[i].resm1 = (float)(res - 1);
    }

    // sort pipeline (recomputed every call — graph replays re-run all of it)
    zero_hist_kernel<<<(NBINS + 1023) / 1024, 1024>>>();
    hist_kernel<<<BSZ / TPB, TPB>>>(x);
    scan_kernel<<<1, 1024>>>();
    scatter_kernel<<<BSZ / TPB, TPB>>>(x);
    hash_embed_kernel<<<BSZ / TPB, TPB>>>(x, emb, out, P);
}

// round 14
// speedup vs baseline: 1.1631x; 1.0014x over previous
#include <cuda_runtime.h>
#include <cuda_bf16.h>
#include <math.h>

// ---------------------------------------------------------------------------
// InstantNGP hash-grid embedding, 16 levels, F=2, T=2^19, 1M points.
//
// R12 = R10 (281.5us: spatial counting sort + R6 compute kernel) with a
// trimmed aux pipeline:
//   * hist_kernel now ALSO stores the Morton key per point (g_keys, 4MB
//     coalesced) — it computes the key anyway.
//   * scatter_kernel reads g_keys (4MB coalesced) instead of re-reading
//     12MB of x and recomputing the key. Expected scatter 23us -> ~14us.
// Main embedding kernel is byte-identical to the R10 winner.
//
// Pipeline (graph-capturable, scratch = __device__ globals):
//   K1 zero 32768-bin histogram
//   K2 histogram + key store
//   K3 single-block exclusive scan
//   K4 scatter -> g_perm (intra-bin order arbitrary; output is written per
//      ORIGINAL point index, so values are order-independent/deterministic)
//   K5 main embedding kernel on permuted points
// ---------------------------------------------------------------------------

#define NLVL 16
#define LOG2_T 19
#define TABLE_SIZE (1u << LOG2_T)
#define HMASK (TABLE_SIZE - 1u)
#define BSZ 1048576
#define PRIME1 2654435761u
#define PRIME2 805459861u
#define TPB 256
#define GRID_RES 32               // 32^3 sort bins
#define NBINS (GRID_RES * GRID_RES * GRID_RES)

__device__ unsigned g_hist[NBINS];
__device__ unsigned g_keys[BSZ];
__device__ unsigned g_perm[BSZ];

struct LevelParams {
    float invgs;   // 1 / grid_size (host-computed via double)
    float resm1;   // (float)(res - 1)
};
struct AllParams {
    LevelParams lp[NLVL];
};

// ---- Morton key helpers ----------------------------------------------------
__device__ __forceinline__ unsigned expand3(unsigned v) {
    v &= 0x3FFu;
    v = (v | (v << 16)) & 0x030000FFu;
    v = (v | (v << 8))  & 0x0300F00Fu;
    v = (v | (v << 4))  & 0x030C30C3u;
    v = (v | (v << 2))  & 0x09249249u;
    return v;
}

__device__ __forceinline__ unsigned point_key(float x0, float x1, float x2) {
    unsigned c0 = (unsigned)fminf(fmaxf(floorf((x0 + 1.0f) * 16.0f), 0.0f), 31.0f);
    unsigned c1 = (unsigned)fminf(fmaxf(floorf((x1 + 1.0f) * 16.0f), 0.0f), 31.0f);
    unsigned c2 = (unsigned)fminf(fmaxf(floorf((x2 + 1.0f) * 16.0f), 0.0f), 31.0f);
    return expand3(c0) | (expand3(c1) << 1) | (expand3(c2) << 2);
}

// ---- K1: zero histogram ----------------------------------------------------
__global__ void zero_hist_kernel() {
    int i = blockIdx.x * blockDim.x + threadIdx.x;
    if (i < NBINS) g_hist[i] = 0u;
}

// ---- K2: histogram + key store ---------------------------------------------
__global__ __launch_bounds__(TPB)
void hist_kernel(const float* __restrict__ x) {
    int i = blockIdx.x * TPB + threadIdx.x;
    const float x0 = x[i * 3 + 0];
    const float x1 = x[i * 3 + 1];
    const float x2 = x[i * 3 + 2];
    const unsigned k = point_key(x0, x1, x2);
    g_keys[i] = k;
    atomicAdd(&g_hist[k], 1u);
}

// ---- K3: single-block exclusive scan over NBINS ----------------------------
__global__ __launch_bounds__(1024)
void scan_kernel() {
    __shared__ unsigned sums[1024];
    const int t = threadIdx.x;
    const int base = t * (NBINS / 1024);          // 32 bins per thread

    unsigned local[NBINS / 1024];
    unsigned run = 0;
#pragma unroll
    for (int j = 0; j < NBINS / 1024; ++j) {
        local[j] = run;
        run += g_hist[base + j];
    }
    sums[t] = run;
    __syncthreads();

    // Hillis-Steele inclusive scan (read before write each step)
    for (int off = 1; off < 1024; off <<= 1) {
        unsigned v = (t >= off) ? sums[t - off] : 0u;
        __syncthreads();
        sums[t] += v;
        __syncthreads();
    }
    const unsigned prefix = sums[t] - run;        // exclusive prefix of this chunk

#pragma unroll
    for (int j = 0; j < NBINS / 1024; ++j)
        g_hist[base + j] = prefix + local[j];
}

// ---- K4: scatter (build permutation) — key read, no recompute --------------
__global__ __launch_bounds__(TPB)
void scatter_kernel() {
    int i = blockIdx.x * TPB + threadIdx.x;
    const unsigned k = g_keys[i];
    unsigned slot = atomicAdd(&g_hist[k], 1u);
    g_perm[slot] = (unsigned)i;
}

// ---- K5: main embedding kernel (byte-identical to R10 winner) --------------
__global__ __launch_bounds__(TPB)
void hash_embed_kernel(const float* __restrict__ x,
                       const float* __restrict__ emb,
                       float* __restrict__ out,
                       AllParams P)
{
    const int i = blockIdx.x * TPB + threadIdx.x;   // BSZ % TPB == 0
    const unsigned p = g_perm[i];

    const float x0 = __ldg(&x[p * 3 + 0]);
    const float x1 = __ldg(&x[p * 3 + 1]);
    const float x2 = __ldg(&x[p * 3 + 2]);

    float2 r[NLVL];

#pragma unroll
    for (int l = 0; l < NLVL; ++l) {
        const float invgs = P.lp[l].invgs;
        const float rm1   = P.lp[l].resm1;

        const float rel0 = (x0 + 1.0f) * invgs;
        const float rel1 = (x1 + 1.0f) * invgs;
        const float rel2 = (x2 + 1.0f) * invgs;

        const float f0 = fminf(fmaxf(floorf(rel0), 0.0f), rm1);
        const float f1 = fminf(fmaxf(floorf(rel1), 0.0f), rm1);
        const float f2 = fminf(fmaxf(floorf(rel2), 0.0f), rm1);

        const float w0 = rel0 - f0;
        const float w1 = rel1 - f1;
        const float w2 = rel2 - f2;

        const unsigned u0 = (unsigned)f0;
        const unsigned u1 = (unsigned)f1;
        const unsigned u2 = (unsigned)f2;

        const bool odd0 = (u0 & 1u) != 0u;

        const unsigned a1 = u0 + 1u;
        const unsigned b0 = u1 * PRIME1;
        const unsigned b1 = b0 + PRIME1;
        const unsigned c0 = u2 * PRIME2;
        const unsigned c1 = c0 + PRIME2;

        const float2* __restrict__ tab =
            (const float2*)emb + (size_t)l * TABLE_SIZE;
        const float4* __restrict__ tab4 = (const float4*)tab;

        const unsigned h00 = (u0 ^ b0 ^ c0) & HMASK;
        const unsigned h10 = (u0 ^ b1 ^ c0) & HMASK;
        const unsigned h01 = (u0 ^ b0 ^ c1) & HMASK;
        const unsigned h11 = (u0 ^ b1 ^ c1) & HMASK;

        // 4 unconditional float4 pair-loads — independent, one round
        const float4 q00 = __ldg(&tab4[h00 >> 1]);
        const float4 q10 = __ldg(&tab4[h10 >> 1]);
        const float4 q01 = __ldg(&tab4[h01 >> 1]);
        const float4 q11 = __ldg(&tab4[h11 >> 1]);

        // 4 predicated float2 loads for odd u0 — same latency round
        float2 e00, e10, e01, e11;
        if (odd0) {
            e00 = __ldg(&tab[(a1 ^ b0 ^ c0) & HMASK]);
            e10 = __ldg(&tab[(a1 ^ b1 ^ c0) & HMASK]);
            e01 = __ldg(&tab[(a1 ^ b0 ^ c1) & HMASK]);
            e11 = __ldg(&tab[(a1 ^ b1 ^ c1) & HMASK]);
        } else {
            e00 = e10 = e01 = e11 = make_float2(0.0f, 0.0f);
        }

        const bool o00 = (h00 & 1u) != 0u;
        const bool o10 = (h10 & 1u) != 0u;
        const bool o01 = (h01 & 1u) != 0u;
        const bool o11 = (h11 & 1u) != 0u;

        const float2 vA00 = o00 ? make_float2(q00.z, q00.w) : make_float2(q00.x, q00.y);
        const float2 vA10 = o10 ? make_float2(q10.z, q10.w) : make_float2(q10.x, q10.y);
        const float2 vA01 = o01 ? make_float2(q01.z, q01.w) : make_float2(q01.x, q01.y);
        const float2 vA11 = o11 ? make_float2(q11.z, q11.w) : make_float2(q11.x, q11.y);

        const float2 vB00 = odd0 ? e00 : (o00 ? make_float2(q00.x, q00.y) : make_float2(q00.z, q00.w));
        const float2 vB10 = odd0 ? e10 : (o10 ? make_float2(q10.x, q10.y) : make_float2(q10.z, q10.w));
        const float2 vB01 = odd0 ? e01 : (o01 ? make_float2(q01.x, q01.y) : make_float2(q01.z, q01.w));
        const float2 vB11 = odd0 ? e11 : (o11 ? make_float2(q11.x, q11.y) : make_float2(q11.z, q11.w));

        const float m0 = 1.0f - w0;
        const float m1 = 1.0f - w1;
        const float m2 = 1.0f - w2;

        const float p00 = m1 * m2;
        const float p10 = w1 * m2;
        const float p01 = m1 * w2;
        const float p11 = w1 * w2;

        const float cx00x = fmaf(w0, vB00.x, m0 * vA00.x);
        const float cx00y = fmaf(w0, vB00.y, m0 * vA00.y);
        const float cx10x = fmaf(w0, vB10.x, m0 * vA10.x);
        const float cx10y = fmaf(w0, vB10.y, m0 * vA10.y);
        const float cx01x = fmaf(w0, vB01.x, m0 * vA01.x);
        const float cx01y = fmaf(w0, vB01.y, m0 * vA01.y);
        const float cx11x = fmaf(w0, vB11.x, m0 * vA11.x);
        const float cx11y = fmaf(w0, vB11.y, m0 * vA11.y);

        float accx = p00 * cx00x;
        float accy = p00 * cx00y;
        accx = fmaf(p10, cx10x, accx);
        accy = fmaf(p10, cx10y, accy);
        accx = fmaf(p01, cx01x, accx);
        accy = fmaf(p01, cx01y, accy);
        accx = fmaf(p11, cx11x, accx);
        accy = fmaf(p11, cx11y, accy);

        r[l].x = accx;
        r[l].y = accy;

        __syncthreads();   // per-level phase-locking (known-good)
    }

    // direct per-thread output (R6 tail)
    float4* __restrict__ o = (float4*)(out + (size_t)p * 32);
#pragma unroll
    for (int k = 0; k < 8; ++k) {
        o[k] = make_float4(r[2 * k].x, r[2 * k].y,
                           r[2 * k + 1].x, r[2 * k + 1].y);
    }
}

extern "C" void kernel_launch(void* const* d_in, const int* in_sizes, int n_in,
                              void* d_out, int out_size)
{
    const float* x   = (const float*)d_in[0];   // (1048576, 3) f32
    const float* emb = (const float*)d_in[1];   // (16, 524288, 2) f32
    float* out = (float*)d_out;                 // (1048576, 32) f32

    // Recompute RESOLUTIONS with the reference's double-precision formula
    // (several floor() results sit exactly on integer boundaries).
    AllParams P;
    const double growth = exp((log(512.0) - log(16.0)) / 15.0);
    for (int i = 0; i < NLVL; ++i) {
        int res = (int)floor(16.0 * pow(growth, (double)i));
        float gsf = (float)(2.0 / (double)res);
        P.lp[i].invgs = (float)(1.0 / (double)gsf);
        P.lp[i].resm1 = (float)(res - 1);
    }

    // sort pipeline (recomputed every call — graph replays re-run all of it)
    zero_hist_kernel<<<(NBINS + 1023) / 1024, 1024>>>();
    hist_kernel<<<BSZ / TPB, TPB>>>(x);
    scan_kernel<<<1, 1024>>>();
    scatter_kernel<<<BSZ / TPB, TPB>>>();
    hash_embed_kernel<<<BSZ / TPB, TPB>>>(x, emb, out, P);
}